// round 1
// baseline (speedup 1.0000x reference)
#include <cuda_runtime.h>
#include <math.h>

#define HID 128
#define NB 4
#define HH 256
#define WW 256
#define NPIX (NB*HH*WW)          // 262144 pixels
#define NL 4

// Ping-pong activation buffers, pixel-major: [pixel][channel]
__device__ float g_buf0[(size_t)NPIX * HID];
__device__ float g_buf1[(size_t)NPIX * HID];
// Combined weights per layer: [l][k=256][o=128]; k<128 -> A = cw^T + (wr+wi)/2, k>=128 -> B = (wr-wi)/2
__device__ float g_wcomb[NL * 2 * HID * HID];
// s(x) = irfft2 bias pattern along row y==0
__device__ float g_sx[WW];

__device__ __forceinline__ float gelu_exact(float v) {
    return 0.5f * v * (1.0f + erff(v * 0.70710678118654752f));
}

// ---------------------------------------------------------------------------
// Build combined weights
// ---------------------------------------------------------------------------
__global__ void prep_w_kernel(const float* __restrict__ wr,
                              const float* __restrict__ wi,
                              const float* __restrict__ cw,
                              float* __restrict__ wcomb)
{
    int idx = blockIdx.x * blockDim.x + threadIdx.x;   // < 4*256*128
    int l = idx >> 15;
    int r = idx & 32767;
    int k = r >> 7;
    int o = r & 127;
    const float* wrl = wr + (size_t)l * HID * HID;
    const float* wil = wi + (size_t)l * HID * HID;
    float v;
    if (k < HID) {
        int i = k;
        v = cw[(size_t)l * HID * HID + o * HID + i]
          + 0.5f * (wrl[i * HID + o] + wil[i * HID + o]);
    } else {
        int i = k - HID;
        v = 0.5f * (wrl[i * HID + o] - wil[i * HID + o]);
    }
    wcomb[idx] = v;
}

// s(x) = -(1/128) * sum_{k=1}^{127} sin(pi*k*x/128)   (row y==0 imag-bias pattern)
__global__ void prep_sx_kernel(float* __restrict__ sx)
{
    int x = threadIdx.x;
    double a = 0.0;
    for (int k = 1; k < 128; k++)
        a += sin(M_PI * (double)k * (double)x / 128.0);
    sx[x] = (float)(-a / 128.0);
}

// ---------------------------------------------------------------------------
// Input transform: h0[pix][c] = gelu( sum_i x[b,i,y,x] * W[i,c] + b[c] )
// ---------------------------------------------------------------------------
__global__ void in_kernel(const float* __restrict__ x,
                          const float* __restrict__ w,
                          const float* __restrict__ bias,
                          float* __restrict__ out)
{
    int pix = blockIdx.x;
    int c = threadIdx.x;
    int b = pix >> 16;
    int yx = pix & 65535;
    const float* xb = x + (size_t)b * 3 * 65536 + yx;
    float x0 = __ldg(xb);
    float x1 = __ldg(xb + 65536);
    float x2 = __ldg(xb + 131072);
    float v = x0 * __ldg(w + c) + x1 * __ldg(w + 128 + c) + x2 * __ldg(w + 256 + c) + __ldg(bias + c);
    out[(size_t)pix * HID + c] = gelu_exact(v);
}

// ---------------------------------------------------------------------------
// Output transform: y[pix] = gelu( h[pix,:] . w + b )   (COUT = 1)
// ---------------------------------------------------------------------------
__global__ void out_kernel(const float* __restrict__ h,
                           const float* __restrict__ w,
                           const float* __restrict__ b,
                           float* __restrict__ out)
{
    int gwarp = (blockIdx.x * blockDim.x + threadIdx.x) >> 5;
    int lane = threadIdx.x & 31;
    if (gwarp >= NPIX) return;
    float4 hv = *(const float4*)(h + (size_t)gwarp * HID + lane * 4);
    float4 wv = *(const float4*)(w + lane * 4);
    float s = hv.x * wv.x + hv.y * wv.y + hv.z * wv.z + hv.w * wv.w;
    #pragma unroll
    for (int o = 16; o; o >>= 1) s += __shfl_xor_sync(0xffffffffu, s, o);
    if (lane == 0) out[gwarp] = gelu_exact(s + __ldg(b));
}

// ---------------------------------------------------------------------------
// Layer kernel: out[p,o] = gelu( sum_i h[p,i]A[i,o] + sum_i h[flip(p),i]B[i,o]
//                                + cb[o] + bias_field(p,o) )
// One block = 128 consecutive pixels (half a row) x 128 outputs, K=256.
// ---------------------------------------------------------------------------
__global__ void __launch_bounds__(256, 2) layer_kernel(
    const float* __restrict__ hin, float* __restrict__ hout,
    const float* __restrict__ wc,   // this layer's [256][128]
    const float* __restrict__ cb,
    const float* __restrict__ brl,
    const float* __restrict__ bil)
{
    __shared__ float Xs[16][128];   // [k][m]
    __shared__ float Ws[16][128];   // [k][o]

    int tid = threadIdx.x;
    int t = blockIdx.x;             // [0, 2048)
    int b = t >> 9;                 // 512 blocks per batch image
    int r = t & 511;
    int j = r >> 1;                 // row order index (pairs y and 256-y adjacent for L2 reuse)
    int xh = r & 1;
    int y;
    if (j == 0)       y = 0;
    else if (j == 1)  y = 128;
    else { int tt = j >> 1; y = (j & 1) ? (256 - tt) : tt; }
    int x0 = xh << 7;
    int yf = (256 - y) & 255;

    const float* hp = hin + (((size_t)(b * 256 + y)) * 256 + x0) * HID;
    const float* hq = hin + (((size_t)(b * 256 + yf)) * 256) * HID;

    // X tile load mapping: 2 threads per pixel row, 8 floats each
    int lm = tid >> 1;
    int half = tid & 1;
    int xfm = (256 - (x0 + lm)) & 255;     // flipped x for pixel lm
    const float* psrc = hp + (size_t)lm * HID + half * 8;
    const float* qsrc = hq + (size_t)xfm * HID + half * 8;

    // W tile load mapping: float4-linear, fully coalesced & conflict-free
    int wrow = tid >> 5;                   // 0..7
    int wcol = tid & 31;

    int tx = tid & 15, ty = tid >> 4;
    float acc[8][8];
    #pragma unroll
    for (int i = 0; i < 8; i++)
        #pragma unroll
        for (int jj = 0; jj < 8; jj++) acc[i][jj] = 0.0f;

    for (int kb = 0; kb < 256; kb += 16) {
        const float* src = (kb < 128) ? (psrc + kb) : (qsrc + (kb - 128));
        float4 v0 = *(const float4*)src;
        float4 v1 = *(const float4*)(src + 4);
        const float* wsrc = wc + (size_t)(kb + wrow) * HID + wcol * 4;
        float4 w0 = *(const float4*)wsrc;
        float4 w1 = *(const float4*)(wsrc + 8 * HID);

        __syncthreads();
        int kh = half * 8;
        Xs[kh + 0][lm] = v0.x; Xs[kh + 1][lm] = v0.y;
        Xs[kh + 2][lm] = v0.z; Xs[kh + 3][lm] = v0.w;
        Xs[kh + 4][lm] = v1.x; Xs[kh + 5][lm] = v1.y;
        Xs[kh + 6][lm] = v1.z; Xs[kh + 7][lm] = v1.w;
        ((float4*)Ws)[tid] = w0;
        ((float4*)Ws)[tid + 256] = w1;
        __syncthreads();

        #pragma unroll
        for (int k = 0; k < 16; k++) {
            float am[8], bn[8];
            *(float4*)&am[0] = *(const float4*)&Xs[k][ty * 8];
            *(float4*)&am[4] = *(const float4*)&Xs[k][ty * 8 + 4];
            *(float4*)&bn[0] = *(const float4*)&Ws[k][tx * 8];
            *(float4*)&bn[4] = *(const float4*)&Ws[k][tx * 8 + 4];
            #pragma unroll
            for (int i = 0; i < 8; i++)
                #pragma unroll
                for (int jj = 0; jj < 8; jj++)
                    acc[i][jj] = fmaf(am[i], bn[jj], acc[i][jj]);
        }
    }

    // Epilogue: bias + gelu + store
    float cbv[8], brv[8], biv[8];
    #pragma unroll
    for (int jj = 0; jj < 8; jj++) {
        int o = tx * 8 + jj;
        cbv[jj] = __ldg(cb + o);
        brv[jj] = __ldg(brl + o);
        biv[jj] = __ldg(bil + o);
    }
    bool row0 = (y == 0);
    float* orow = hout + (((size_t)(b * 256 + y)) * 256 + x0) * HID;
    #pragma unroll
    for (int i = 0; i < 8; i++) {
        int m = ty * 8 + i;
        int xx = x0 + m;
        float sxv = row0 ? g_sx[xx] : 0.0f;
        float outv[8];
        #pragma unroll
        for (int jj = 0; jj < 8; jj++) {
            float v = acc[i][jj] + cbv[jj];
            if (row0) {
                v += biv[jj] * sxv;
                if (xx == 0) v += brv[jj];
            }
            outv[jj] = gelu_exact(v);
        }
        float* dst = orow + (size_t)m * HID + tx * 8;
        *(float4*)dst = *(float4*)&outv[0];
        *(float4*)(dst + 4) = *(float4*)&outv[4];
    }
}

// ---------------------------------------------------------------------------
extern "C" void kernel_launch(void* const* d_in, const int* in_sizes, int n_in,
                              void* d_out, int out_size)
{
    const float* x   = (const float*)d_in[0];
    const float* liw = (const float*)d_in[1];
    const float* lib = (const float*)d_in[2];
    const float* wr  = (const float*)d_in[3];
    const float* wi  = (const float*)d_in[4];
    const float* br  = (const float*)d_in[5];
    const float* bi  = (const float*)d_in[6];
    const float* cw  = (const float*)d_in[7];
    const float* cb  = (const float*)d_in[8];
    const float* low = (const float*)d_in[9];
    const float* lob = (const float*)d_in[10];
    float* out = (float*)d_out;

    float *buf0, *buf1, *wcomb, *sx;
    cudaGetSymbolAddress((void**)&buf0, g_buf0);
    cudaGetSymbolAddress((void**)&buf1, g_buf1);
    cudaGetSymbolAddress((void**)&wcomb, g_wcomb);
    cudaGetSymbolAddress((void**)&sx, g_sx);

    prep_w_kernel<<<512, 256>>>(wr, wi, cw, wcomb);
    prep_sx_kernel<<<1, 256>>>(sx);
    in_kernel<<<NPIX, 128>>>(x, liw, lib, buf0);

    float* bufs[2] = { buf0, buf1 };
    for (int l = 0; l < NL; l++) {
        layer_kernel<<<2048, 256>>>(bufs[l & 1], bufs[(l & 1) ^ 1],
                                    wcomb + (size_t)l * 2 * HID * HID,
                                    cb + l * HID, br + l * HID, bi + l * HID);
    }
    // after 4 layers result is back in buf0
    out_kernel<<<NPIX / 8, 256>>>(buf0, low, lob, out);
}

// round 3
// speedup vs baseline: 2.1493x; 2.1493x over previous
#include <cuda_runtime.h>
#include <cuda_bf16.h>
#include <math.h>
#include <stdint.h>

#define HID 128
#define NPIX (4*256*256)
#define NL 4
#define NTILES 2048
#define GRID_LAYER 152

// ---------------------------------------------------------------------------
// Device globals
// ---------------------------------------------------------------------------
__device__ float g_buf0[(size_t)NPIX * HID];
__device__ float g_buf1[(size_t)NPIX * HID];
// Combined weights as the exact smem image:
// [l][kc(4)][chunk 16KB: n=128 rows x 64 bf16 (k), SW128-swizzled], hi & lo parts
__device__ unsigned short g_whi[NL * 4 * 8192];
__device__ unsigned short g_wlo[NL * 4 * 8192];
__device__ float g_sx[256];

// ---------------------------------------------------------------------------
// Helpers
// ---------------------------------------------------------------------------
__device__ __forceinline__ uint32_t smem_u32(const void* p) {
    uint32_t a;
    asm("{ .reg .u64 t; cvta.to.shared.u64 t, %1; cvt.u32.u64 %0, t; }" : "=r"(a) : "l"(p));
    return a;
}
__device__ __forceinline__ void ldsm4(uint32_t& r0, uint32_t& r1, uint32_t& r2, uint32_t& r3, uint32_t addr) {
    asm volatile("ldmatrix.sync.aligned.m8n8.x4.shared.b16 {%0,%1,%2,%3}, [%4];"
        : "=r"(r0), "=r"(r1), "=r"(r2), "=r"(r3) : "r"(addr));
}
__device__ __forceinline__ void mma16816(float* d, const uint32_t* a, uint32_t b0, uint32_t b1) {
    asm volatile("mma.sync.aligned.m16n8k16.row.col.f32.bf16.bf16.f32 "
        "{%0,%1,%2,%3}, {%4,%5,%6,%7}, {%8,%9}, {%0,%1,%2,%3};"
        : "+f"(d[0]), "+f"(d[1]), "+f"(d[2]), "+f"(d[3])
        : "r"(a[0]), "r"(a[1]), "r"(a[2]), "r"(a[3]), "r"(b0), "r"(b1));
}
__device__ __forceinline__ float gelu_exact(float v) {
    return 0.5f * v * (1.0f + erff(v * 0.70710678118654752f));
}
__device__ __forceinline__ uint32_t pack_hi2(float a, float b) {
    return __byte_perm(__float_as_uint(a), __float_as_uint(b), 0x7632);
}
__device__ __forceinline__ uint32_t pack_lo2(float a, float b) {
    float ra = a - __uint_as_float(__float_as_uint(a) & 0xffff0000u);
    float rb = b - __uint_as_float(__float_as_uint(b) & 0xffff0000u);
    __nv_bfloat162 p = __floats2bfloat162_rn(ra, rb);
    return *reinterpret_cast<uint32_t*>(&p);
}

// ---------------------------------------------------------------------------
// SMEM layout (relative to 128B-aligned base)
// ---------------------------------------------------------------------------
#define SM_BHI   0u            // 4 chunks x 16KB
#define SM_BLO   65536u
#define SM_A(s)  (131072u + (uint32_t)(s) * 32768u)   // hi at +0, lo at +16384
#define SM_BIAS  196608u
#define SM_DYN   (196608 + 1536 + 256)

// ---------------------------------------------------------------------------
// Weight prep: combined weights -> bf16 hi/lo, swizzled smem image
// layout per chunk: row = o (n), col = kl (64 bf16 = 128B row), SW128
// ---------------------------------------------------------------------------
__global__ void prep_w_kernel(const float* __restrict__ wr,
                              const float* __restrict__ wi,
                              const float* __restrict__ cw,
                              unsigned short* __restrict__ whi,
                              unsigned short* __restrict__ wlo)
{
    int idx = blockIdx.x * blockDim.x + threadIdx.x;   // < 131072
    int l = idx >> 15;
    int rem = idx & 32767;
    int kc = rem >> 13;
    int rem2 = rem & 8191;
    int o = rem2 >> 6;
    int kl = rem2 & 63;
    int kg = kc * 64 + kl;
    const float* wrl = wr + (size_t)l * 16384;
    const float* wil = wi + (size_t)l * 16384;
    float v;
    if (kg < 128)
        v = cw[(size_t)l * 16384 + o * 128 + kg] + 0.5f * (wrl[kg * 128 + o] + wil[kg * 128 + o]);
    else {
        int i = kg - 128;
        v = 0.5f * (wrl[i * 128 + o] - wil[i * 128 + o]);
    }
    uint32_t u = __float_as_uint(v);
    float hf = __uint_as_float(u & 0xffff0000u);
    float lo = v - hf;
    uint32_t off = (uint32_t)o * 128 + kl * 2;
    off ^= (off >> 3) & 0x70;               // SW128 swizzle
    size_t cbase = (size_t)(l * 4 + kc) * 8192;
    whi[cbase + (off >> 1)] = (unsigned short)(u >> 16);
    __nv_bfloat16 lb = __float2bfloat16_rn(lo);
    wlo[cbase + (off >> 1)] = __bfloat16_as_ushort(lb);
}

// Closed-form Dirichlet: s(x) = -(1/128) * sum_{k=1}^{127} sin(pi*k*x/128)
__global__ void prep_sx_kernel(float* __restrict__ sx)
{
    int x = threadIdx.x;
    double s = 0.0;
    if (x) {
        double th = M_PI * (double)x / 128.0;
        s = sin(63.5 * th) * sin(64.0 * th) / sin(0.5 * th);
    }
    sx[x] = (float)(-s / 128.0);
}

// ---------------------------------------------------------------------------
// Input transform
// ---------------------------------------------------------------------------
__global__ void in_kernel(const float* __restrict__ x,
                          const float* __restrict__ w,
                          const float* __restrict__ bias,
                          float* __restrict__ out)
{
    int pix = blockIdx.x;
    int c = threadIdx.x;
    int b = pix >> 16;
    int yx = pix & 65535;
    const float* xb = x + (size_t)b * 3 * 65536 + yx;
    float x0 = __ldg(xb);
    float x1 = __ldg(xb + 65536);
    float x2 = __ldg(xb + 131072);
    float v = x0 * __ldg(w + c) + x1 * __ldg(w + 128 + c) + x2 * __ldg(w + 256 + c) + __ldg(bias + c);
    out[(size_t)pix * HID + c] = gelu_exact(v);
}

// ---------------------------------------------------------------------------
// Output transform (COUT = 1)
// ---------------------------------------------------------------------------
__global__ void out_kernel(const float* __restrict__ h,
                           const float* __restrict__ w,
                           const float* __restrict__ b,
                           float* __restrict__ out)
{
    int gwarp = (blockIdx.x * blockDim.x + threadIdx.x) >> 5;
    int lane = threadIdx.x & 31;
    if (gwarp >= NPIX) return;
    float4 hv = *(const float4*)(h + (size_t)gwarp * HID + lane * 4);
    float4 wv = *(const float4*)(w + lane * 4);
    float s = hv.x * wv.x + hv.y * wv.y + hv.z * wv.z + hv.w * wv.w;
    #pragma unroll
    for (int o = 16; o; o >>= 1) s += __shfl_xor_sync(0xffffffffu, s, o);
    if (lane == 0) out[gwarp] = gelu_exact(s + __ldg(b));
}

// ---------------------------------------------------------------------------
// Layer kernel: persistent, mma.sync bf16-split GEMM on tensor pipe
// ---------------------------------------------------------------------------
__global__ void __launch_bounds__(512, 1) layer_kernel(
    const float* __restrict__ hin, float* __restrict__ hout,
    const uint4* __restrict__ whiL, const uint4* __restrict__ wloL,
    const float* __restrict__ cbp, const float* __restrict__ brp,
    const float* __restrict__ bip)
{
    extern __shared__ char dsm_raw[];
    uint32_t raw = smem_u32(dsm_raw);
    uint32_t sbase = (raw + 127) & ~127u;
    char* sm = dsm_raw + (sbase - raw);

    int tid = threadIdx.x;
    int wid = tid >> 5;
    int lane = tid & 31;
    int wm = wid & 3;       // warp M index (4)
    int wn = wid >> 2;      // warp N index (4)

    // ---- preload B (128KB) + biases once ----
    {
        uint4* bh = (uint4*)(sm + SM_BHI);
        uint4* bl = (uint4*)(sm + SM_BLO);
        #pragma unroll
        for (int q = 0; q < 8; q++) {
            bh[tid + q * 512] = __ldg(whiL + tid + q * 512);
            bl[tid + q * 512] = __ldg(wloL + tid + q * 512);
        }
        float* bs = (float*)(sm + SM_BIAS);
        if (tid < 128) {
            bs[tid]       = __ldg(cbp + tid);
            bs[128 + tid] = __ldg(brp + tid);
            bs[256 + tid] = __ldg(bip + tid);
        }
    }
    __syncthreads();

    // ---- per-lane ldmatrix address components ----
    int grp = lane >> 3, lr = lane & 7;
    uint32_t xm = (uint32_t)(lr << 4);                 // swizzle xor
    // A: matrix order a0(m0-7,k0-7) a1(m8-15,k0-7) a2(m0-7,k8-15) a3(m8-15,k8-15)
    uint32_t a_rowadd = (uint32_t)(lr + ((grp & 1) << 3));
    uint32_t a_c16 = (uint32_t)((grp >> 1) << 4);
    // B: b0(n0-7) b1(n0-7,k8) b0(n8-15) b1(n8-15,k8)
    uint32_t b_rowadd = (uint32_t)(lr + ((grp >> 1) << 3));
    uint32_t b_c16 = (uint32_t)((grp & 1) << 4);

    uint32_t arow[2], brow[2];
    #pragma unroll
    for (int mt = 0; mt < 2; mt++) arow[mt] = (uint32_t)(wm * 32 + mt * 16 + a_rowadd) * 128u;
    #pragma unroll
    for (int np = 0; np < 2; np++) brow[np] = (uint32_t)(wn * 32 + np * 16 + b_rowadd) * 128u;

    // conversion mapping: 512 threads, m = tid>>2, 16 k per thread
    int cm = tid >> 2;
    int ckq = (tid & 3) * 16;
    uint32_t c_off0 = (uint32_t)cm * 128u + (((uint32_t)ckq * 2u) ^ ((uint32_t)(cm & 7) << 4));
    uint32_t c_off1 = (uint32_t)cm * 128u + (((uint32_t)ckq * 2u + 16u) ^ ((uint32_t)(cm & 7) << 4));

    const float* cbS = (const float*)(sm + SM_BIAS);
    const float* brS = cbS + 128;
    const float* biS = cbS + 256;

    for (int t = blockIdx.x; t < NTILES; t += GRID_LAYER) {
        // tile decode: pairs (y, 256-y) and x-halves adjacent for flip L2 reuse
        int b = t >> 9, r = t & 511, j = r >> 1, xh = r & 1;
        int y;
        if (j == 0) y = 0;
        else if (j == 1) y = 128;
        else { int tt = j >> 1; y = (j & 1) ? (256 - tt) : tt; }
        int x0 = xh << 7;
        int yf = (256 - y) & 255;
        size_t base = ((size_t)(b * 256 + y)) * 256 + x0;
        size_t fbase = ((size_t)(b * 256 + yf)) * 256;

        int xf = (256 - (x0 + cm)) & 255;
        const float* srcD = hin + (base + cm) * 128 + ckq;
        const float* srcF = hin + (fbase + xf) * 128 + ckq;

        float acc[2][4][4];
        #pragma unroll
        for (int mt = 0; mt < 2; mt++)
            #pragma unroll
            for (int nt = 0; nt < 4; nt++)
                #pragma unroll
                for (int q = 0; q < 4; q++) acc[mt][nt][q] = 0.0f;

        // ---- convert chunk 0 into buf0 ----
        {
            float4 pre[4];
            #pragma unroll
            for (int q = 0; q < 4; q++) pre[q] = __ldg((const float4*)srcD + q);
            char* hi = sm + SM_A(0);
            char* lo = hi + 16384;
            uint4 h0, h1, l0, l1;
            h0.x = pack_hi2(pre[0].x, pre[0].y); l0.x = pack_lo2(pre[0].x, pre[0].y);
            h0.y = pack_hi2(pre[0].z, pre[0].w); l0.y = pack_lo2(pre[0].z, pre[0].w);
            h0.z = pack_hi2(pre[1].x, pre[1].y); l0.z = pack_lo2(pre[1].x, pre[1].y);
            h0.w = pack_hi2(pre[1].z, pre[1].w); l0.w = pack_lo2(pre[1].z, pre[1].w);
            h1.x = pack_hi2(pre[2].x, pre[2].y); l1.x = pack_lo2(pre[2].x, pre[2].y);
            h1.y = pack_hi2(pre[2].z, pre[2].w); l1.y = pack_lo2(pre[2].z, pre[2].w);
            h1.z = pack_hi2(pre[3].x, pre[3].y); l1.z = pack_lo2(pre[3].x, pre[3].y);
            h1.w = pack_hi2(pre[3].z, pre[3].w); l1.w = pack_lo2(pre[3].z, pre[3].w);
            *(uint4*)(hi + c_off0) = h0; *(uint4*)(hi + c_off1) = h1;
            *(uint4*)(lo + c_off0) = l0; *(uint4*)(lo + c_off1) = l1;
        }
        __syncthreads();

        #pragma unroll
        for (int kc = 0; kc < 4; kc++) {
            // prefetch next chunk's source
            float4 pre[4];
            if (kc < 3) {
                const float* nsrc = (kc == 0) ? (srcD + 64) : (kc == 1) ? srcF : (srcF + 64);
                #pragma unroll
                for (int q = 0; q < 4; q++) pre[q] = __ldg((const float4*)nsrc + q);
            }

            // ---- MMA over chunk kc from buf[kc&1] ----
            uint32_t aHi = sbase + SM_A(kc & 1);
            uint32_t aLo = aHi + 16384u;
            uint32_t bHi = sbase + SM_BHI + (uint32_t)kc * 16384u;
            uint32_t bLo = bHi + 65536u;

            #pragma unroll
            for (int ks = 0; ks < 4; ks++) {
                uint32_t acb = ((uint32_t)(ks * 32) + a_c16) ^ xm;
                uint32_t bcb = ((uint32_t)(ks * 32) + b_c16) ^ xm;
                uint32_t ah[2][4], al[2][4], bh[2][4], bl[2][4];
                #pragma unroll
                for (int mt = 0; mt < 2; mt++) {
                    ldsm4(ah[mt][0], ah[mt][1], ah[mt][2], ah[mt][3], aHi + arow[mt] + acb);
                    ldsm4(al[mt][0], al[mt][1], al[mt][2], al[mt][3], aLo + arow[mt] + acb);
                }
                #pragma unroll
                for (int np = 0; np < 2; np++) {
                    ldsm4(bh[np][0], bh[np][1], bh[np][2], bh[np][3], bHi + brow[np] + bcb);
                    ldsm4(bl[np][0], bl[np][1], bl[np][2], bl[np][3], bLo + brow[np] + bcb);
                }
                #pragma unroll
                for (int mt = 0; mt < 2; mt++) {
                    #pragma unroll
                    for (int nt = 0; nt < 4; nt++) {
                        int np = nt >> 1, half = (nt & 1) * 2;
                        mma16816(acc[mt][nt], ah[mt], bh[np][half], bh[np][half + 1]);
                        mma16816(acc[mt][nt], ah[mt], bl[np][half], bl[np][half + 1]);
                        mma16816(acc[mt][nt], al[mt], bh[np][half], bh[np][half + 1]);
                    }
                }
            }

            // ---- convert prefetched chunk into the other buffer ----
            if (kc < 3) {
                char* hi = sm + SM_A((kc + 1) & 1);
                char* lo = hi + 16384;
                uint4 h0, h1, l0, l1;
                h0.x = pack_hi2(pre[0].x, pre[0].y); l0.x = pack_lo2(pre[0].x, pre[0].y);
                h0.y = pack_hi2(pre[0].z, pre[0].w); l0.y = pack_lo2(pre[0].z, pre[0].w);
                h0.z = pack_hi2(pre[1].x, pre[1].y); l0.z = pack_lo2(pre[1].x, pre[1].y);
                h0.w = pack_hi2(pre[1].z, pre[1].w); l0.w = pack_lo2(pre[1].z, pre[1].w);
                h1.x = pack_hi2(pre[2].x, pre[2].y); l1.x = pack_lo2(pre[2].x, pre[2].y);
                h1.y = pack_hi2(pre[2].z, pre[2].w); l1.y = pack_lo2(pre[2].z, pre[2].w);
                h1.z = pack_hi2(pre[3].x, pre[3].y); l1.z = pack_lo2(pre[3].x, pre[3].y);
                h1.w = pack_hi2(pre[3].z, pre[3].w); l1.w = pack_lo2(pre[3].z, pre[3].w);
                *(uint4*)(hi + c_off0) = h0; *(uint4*)(hi + c_off1) = h1;
                *(uint4*)(lo + c_off0) = l0; *(uint4*)(lo + c_off1) = l1;
            }
            __syncthreads();
        }

        // ---- epilogue: bias + gelu + store ----
        bool row0 = (y == 0);
        #pragma unroll
        for (int mt = 0; mt < 2; mt++) {
            #pragma unroll
            for (int rh = 0; rh < 2; rh++) {
                int m = wm * 32 + mt * 16 + (lane >> 2) + rh * 8;
                int xx = x0 + m;
                float sxv = row0 ? g_sx[xx] : 0.0f;
                float* orow = hout + (base + m) * 128;
                #pragma unroll
                for (int nt = 0; nt < 4; nt++) {
                    int n = wn * 32 + nt * 8 + (lane & 3) * 2;
                    float v0 = acc[mt][nt][rh * 2 + 0] + cbS[n];
                    float v1 = acc[mt][nt][rh * 2 + 1] + cbS[n + 1];
                    if (row0) {
                        v0 += biS[n] * sxv;
                        v1 += biS[n + 1] * sxv;
                        if (xx == 0) { v0 += brS[n]; v1 += brS[n + 1]; }
                    }
                    float2 o;
                    o.x = gelu_exact(v0);
                    o.y = gelu_exact(v1);
                    *(float2*)(orow + n) = o;
                }
            }
        }
        // no barrier needed: buf0 last read at kc=2 (barrier after), buf1 at kc=3
    }
}

// ---------------------------------------------------------------------------
extern "C" void kernel_launch(void* const* d_in, const int* in_sizes, int n_in,
                              void* d_out, int out_size)
{
    const float* x   = (const float*)d_in[0];
    const float* liw = (const float*)d_in[1];
    const float* lib = (const float*)d_in[2];
    const float* wr  = (const float*)d_in[3];
    const float* wi  = (const float*)d_in[4];
    const float* br  = (const float*)d_in[5];
    const float* bi  = (const float*)d_in[6];
    const float* cw  = (const float*)d_in[7];
    const float* cb  = (const float*)d_in[8];
    const float* low = (const float*)d_in[9];
    const float* lob = (const float*)d_in[10];
    float* out = (float*)d_out;

    float *buf0, *buf1, *sx;
    unsigned short *whi, *wlo;
    cudaGetSymbolAddress((void**)&buf0, g_buf0);
    cudaGetSymbolAddress((void**)&buf1, g_buf1);
    cudaGetSymbolAddress((void**)&whi, g_whi);
    cudaGetSymbolAddress((void**)&wlo, g_wlo);
    cudaGetSymbolAddress((void**)&sx, g_sx);

    cudaFuncSetAttribute(layer_kernel, cudaFuncAttributeMaxDynamicSharedMemorySize, SM_DYN);

    prep_w_kernel<<<512, 256>>>(wr, wi, cw, whi, wlo);
    prep_sx_kernel<<<1, 256>>>(sx);
    in_kernel<<<NPIX, 128>>>(x, liw, lib, buf0);

    float* bufs[2] = { buf0, buf1 };
    for (int l = 0; l < NL; l++) {
        layer_kernel<<<GRID_LAYER, 512, SM_DYN>>>(
            bufs[l & 1], bufs[(l & 1) ^ 1],
            (const uint4*)(whi + (size_t)l * 4 * 8192),
            (const uint4*)(wlo + (size_t)l * 4 * 8192),
            cb + l * HID, br + l * HID, bi + l * HID);
    }
    out_kernel<<<NPIX / 8, 256>>>(buf0, low, lob, out);
}

// round 4
// speedup vs baseline: 2.2082x; 1.0274x over previous
#include <cuda_runtime.h>
#include <cuda_bf16.h>
#include <math.h>
#include <stdint.h>

#define HID 128
#define NPIX (4*256*256)
#define NL 4
#define NTILES 2048
#define GRID_LAYER 152

// ---------------------------------------------------------------------------
// Device globals
// ---------------------------------------------------------------------------
__device__ float g_buf0[(size_t)NPIX * HID];
__device__ float g_buf1[(size_t)NPIX * HID];
__device__ unsigned short g_whi[NL * 4 * 8192];
__device__ unsigned short g_wlo[NL * 4 * 8192];
__device__ float g_sx[256];

// ---------------------------------------------------------------------------
// Helpers
// ---------------------------------------------------------------------------
__device__ __forceinline__ uint32_t smem_u32(const void* p) {
    uint32_t a;
    asm("{ .reg .u64 t; cvta.to.shared.u64 t, %1; cvt.u32.u64 %0, t; }" : "=r"(a) : "l"(p));
    return a;
}
__device__ __forceinline__ void ldsm4(uint32_t& r0, uint32_t& r1, uint32_t& r2, uint32_t& r3, uint32_t addr) {
    asm volatile("ldmatrix.sync.aligned.m8n8.x4.shared.b16 {%0,%1,%2,%3}, [%4];"
        : "=r"(r0), "=r"(r1), "=r"(r2), "=r"(r3) : "r"(addr));
}
__device__ __forceinline__ void mma16816(float* d, const uint32_t* a, uint32_t b0, uint32_t b1) {
    asm volatile("mma.sync.aligned.m16n8k16.row.col.f32.bf16.bf16.f32 "
        "{%0,%1,%2,%3}, {%4,%5,%6,%7}, {%8,%9}, {%0,%1,%2,%3};"
        : "+f"(d[0]), "+f"(d[1]), "+f"(d[2]), "+f"(d[3])
        : "r"(a[0]), "r"(a[1]), "r"(a[2]), "r"(a[3]), "r"(b0), "r"(b1));
}
#define BAR_SYNC(id, cnt)   asm volatile("bar.sync %0, %1;"   :: "r"(id), "r"(cnt) : "memory")
#define BAR_ARRIVE(id, cnt) asm volatile("bar.arrive %0, %1;" :: "r"(id), "r"(cnt) : "memory")
#define MEMBAR_CTA()        asm volatile("membar.cta;" ::: "memory")

__device__ __forceinline__ float gelu_exact(float v) {
    return 0.5f * v * (1.0f + erff(v * 0.70710678118654752f));
}
__device__ __forceinline__ uint32_t pack_hi2(float a, float b) {
    return __byte_perm(__float_as_uint(a), __float_as_uint(b), 0x7632);
}
__device__ __forceinline__ uint32_t pack_lo2(float a, float b) {
    float ra = a - __uint_as_float(__float_as_uint(a) & 0xffff0000u);
    float rb = b - __uint_as_float(__float_as_uint(b) & 0xffff0000u);
    __nv_bfloat162 p = __floats2bfloat162_rn(ra, rb);
    return *reinterpret_cast<uint32_t*>(&p);
}
__device__ __forceinline__ void decode_tile(int t, int& b, int& y, int& x0) {
    b = t >> 9;
    int r = t & 511;
    int j = r >> 1;
    x0 = (r & 1) << 7;
    if (j == 0) y = 0;
    else if (j == 1) y = 128;
    else { int tt = j >> 1; y = (j & 1) ? (256 - tt) : tt; }
}

// ---------------------------------------------------------------------------
// SMEM layout (offsets from 128B-aligned base)
// ---------------------------------------------------------------------------
#define SM_BHI   0u             // 4 chunks x 16KB
#define SM_BLO   65536u
#define SM_A(s)  (131072u + (uint32_t)(s) * 32768u)   // hi 16KB + lo 16KB per stage
#define SM_BIAS  196608u        // cb[128], br[128], bi[128]
#define SM_RED   198144u        // 2 x 128 floats
#define SM_LOW   199168u        // low[128], lob
#define SM_DYN   (199168 + 544 + 128)

// ---------------------------------------------------------------------------
// Weight prep (combined weights -> bf16 hi/lo, swizzled smem image)
// ---------------------------------------------------------------------------
__global__ void prep_w_kernel(const float* __restrict__ wr,
                              const float* __restrict__ wi,
                              const float* __restrict__ cw,
                              unsigned short* __restrict__ whi,
                              unsigned short* __restrict__ wlo)
{
    int idx = blockIdx.x * blockDim.x + threadIdx.x;   // < 131072
    int l = idx >> 15;
    int rem = idx & 32767;
    int kc = rem >> 13;
    int rem2 = rem & 8191;
    int o = rem2 >> 6;
    int kl = rem2 & 63;
    int kg = kc * 64 + kl;
    const float* wrl = wr + (size_t)l * 16384;
    const float* wil = wi + (size_t)l * 16384;
    float v;
    if (kg < 128)
        v = cw[(size_t)l * 16384 + o * 128 + kg] + 0.5f * (wrl[kg * 128 + o] + wil[kg * 128 + o]);
    else {
        int i = kg - 128;
        v = 0.5f * (wrl[i * 128 + o] - wil[i * 128 + o]);
    }
    uint32_t u = __float_as_uint(v);
    float hf = __uint_as_float(u & 0xffff0000u);
    float lo = v - hf;
    uint32_t off = (uint32_t)o * 128 + kl * 2;
    off ^= (off >> 3) & 0x70;
    size_t cbase = (size_t)(l * 4 + kc) * 8192;
    whi[cbase + (off >> 1)] = (unsigned short)(u >> 16);
    __nv_bfloat16 lb = __float2bfloat16_rn(lo);
    wlo[cbase + (off >> 1)] = __bfloat16_as_ushort(lb);
}

// Closed-form Dirichlet: s(x) = -(1/128) * sum_{k=1}^{127} sin(pi*k*x/128)
__global__ void prep_sx_kernel(float* __restrict__ sx)
{
    int x = threadIdx.x;
    double s = 0.0;
    if (x) {
        double th = M_PI * (double)x / 128.0;
        s = sin(63.5 * th) * sin(64.0 * th) / sin(0.5 * th);
    }
    sx[x] = (float)(-s / 128.0);
}

// ---------------------------------------------------------------------------
// Input transform: 32 threads per pixel, float4 writes
// ---------------------------------------------------------------------------
__global__ void in_kernel(const float* __restrict__ x,
                          const float* __restrict__ w,
                          const float* __restrict__ bias,
                          float* __restrict__ out)
{
    int gid = blockIdx.x * blockDim.x + threadIdx.x;
    int pix = gid >> 5;
    int c4 = (gid & 31) << 2;
    int b = pix >> 16;
    int yx = pix & 65535;
    const float* xb = x + (size_t)b * 196608 + yx;
    float x0 = __ldg(xb);
    float x1 = __ldg(xb + 65536);
    float x2 = __ldg(xb + 131072);
    float4 w0 = __ldg((const float4*)(w + c4));
    float4 w1 = __ldg((const float4*)(w + 128 + c4));
    float4 w2 = __ldg((const float4*)(w + 256 + c4));
    float4 bb = __ldg((const float4*)(bias + c4));
    float4 o;
    o.x = gelu_exact(x0 * w0.x + x1 * w1.x + x2 * w2.x + bb.x);
    o.y = gelu_exact(x0 * w0.y + x1 * w1.y + x2 * w2.y + bb.y);
    o.z = gelu_exact(x0 * w0.z + x1 * w1.z + x2 * w2.z + bb.z);
    o.w = gelu_exact(x0 * w0.w + x1 * w1.w + x2 * w2.w + bb.w);
    *(float4*)(out + (size_t)pix * HID + c4) = o;
}

// ---------------------------------------------------------------------------
// Layer kernel: warp-specialized producer/consumer, bf16 3-combo MMA
// warps 0-7 consumers (MMA), warps 8-15 producers (convert)
// ---------------------------------------------------------------------------
__global__ void __launch_bounds__(512, 1) layer_kernel(
    const float* __restrict__ hin, float* __restrict__ hout,
    const uint4* __restrict__ whiL, const uint4* __restrict__ wloL,
    const float* __restrict__ cbp, const float* __restrict__ brp,
    const float* __restrict__ bip,
    const float* __restrict__ lowp, const float* __restrict__ lobp,
    float* __restrict__ gout, int fuse)
{
    extern __shared__ char dsm_raw[];
    uint32_t raw = smem_u32(dsm_raw);
    uint32_t sbase = (raw + 127) & ~127u;
    char* sm = dsm_raw + (sbase - raw);

    int tid = threadIdx.x;
    int wid = tid >> 5;
    int lane = tid & 31;

    // ---- preload B (128KB) + biases + low once ----
    {
        uint4* bh = (uint4*)(sm + SM_BHI);
        uint4* bl = (uint4*)(sm + SM_BLO);
        #pragma unroll
        for (int q = 0; q < 8; q++) {
            bh[tid + q * 512] = __ldg(whiL + tid + q * 512);
            bl[tid + q * 512] = __ldg(wloL + tid + q * 512);
        }
        float* bs = (float*)(sm + SM_BIAS);
        if (tid < 128) {
            bs[tid]       = __ldg(cbp + tid);
            bs[128 + tid] = __ldg(brp + tid);
            bs[256 + tid] = __ldg(bip + tid);
        }
        if (fuse) {
            float* lw = (float*)(sm + SM_LOW);
            if (tid < 128) lw[tid] = __ldg(lowp + tid);
            if (tid == 0)  lw[128] = __ldg(lobp);
        }
    }
    __syncthreads();

    int nloc = (NTILES - blockIdx.x + GRID_LAYER - 1) / GRID_LAYER;

    if (wid >= 8) {
        // ================= PRODUCER =================
        int ptid = tid - 256;
        int m = ptid >> 1;
        int khalf = ptid & 1;
        uint32_t swz = (uint32_t)(m & 7) << 4;
        uint32_t stoff[4];
        #pragma unroll
        for (int q = 0; q < 4; q++)
            stoff[q] = (uint32_t)m * 128u + (((uint32_t)(khalf * 64 + q * 16)) ^ swz);

        int total = nloc * 4;

        // src pointer for chunk g
        auto src_for = [&](int g) -> const float* {
            int t = blockIdx.x + (g >> 2) * GRID_LAYER;
            int b, y, x0;
            decode_tile(t, b, y, x0);
            int kc = g & 3;
            if (kc < 2) {
                size_t base = ((size_t)(b * 256 + y)) * 256 + x0;
                return hin + (base + m) * 128 + kc * 64 + khalf * 32;
            } else {
                int yf = (256 - y) & 255;
                size_t fbase = ((size_t)(b * 256 + yf)) * 256;
                int xf = (256 - (x0 + m)) & 255;
                return hin + (fbase + xf) * 128 + (kc - 2) * 64 + khalf * 32;
            }
        };

        float4 v[8];
        {
            const float* sp = src_for(0);
            #pragma unroll
            for (int q = 0; q < 8; q++) v[q] = __ldg((const float4*)sp + q);
        }
        for (int g = 0; g < total; g++) {
            // pack current chunk
            uint4 H[4], L[4];
            #pragma unroll
            for (int q = 0; q < 4; q++) {
                float4 f0 = v[2 * q], f1 = v[2 * q + 1];
                H[q].x = pack_hi2(f0.x, f0.y); L[q].x = pack_lo2(f0.x, f0.y);
                H[q].y = pack_hi2(f0.z, f0.w); L[q].y = pack_lo2(f0.z, f0.w);
                H[q].z = pack_hi2(f1.x, f1.y); L[q].z = pack_lo2(f1.x, f1.y);
                H[q].w = pack_hi2(f1.z, f1.w); L[q].w = pack_lo2(f1.z, f1.w);
            }
            // prefetch next chunk
            if (g + 1 < total) {
                const float* sp = src_for(g + 1);
                #pragma unroll
                for (int q = 0; q < 8; q++) v[q] = __ldg((const float4*)sp + q);
            }
            int s = g & 1;
            if (g >= 2) BAR_SYNC(3 + s, 512);
            char* hi = sm + SM_A(s);
            char* lo = hi + 16384;
            #pragma unroll
            for (int q = 0; q < 4; q++) {
                *(uint4*)(hi + stoff[q]) = H[q];
                *(uint4*)(lo + stoff[q]) = L[q];
            }
            MEMBAR_CTA();
            BAR_ARRIVE(1 + s, 512);
        }
    } else {
        // ================= CONSUMER =================
        int wm = wid & 3;       // m group (4): m = wm*32
        int wn = wid >> 2;      // n group (2): n = wn*64
        int grp = lane >> 3, lr = lane & 7;
        uint32_t xm = (uint32_t)(lr << 4);
        uint32_t a_rowadd = (uint32_t)(lr + ((grp & 1) << 3));
        uint32_t a_c16 = (uint32_t)((grp >> 1) << 4);
        uint32_t b_rowadd = (uint32_t)(lr + ((grp >> 1) << 3));
        uint32_t b_c16 = (uint32_t)((grp & 1) << 4);

        uint32_t arow[2], brow[4];
        #pragma unroll
        for (int mt = 0; mt < 2; mt++) arow[mt] = (uint32_t)(wm * 32 + mt * 16 + a_rowadd) * 128u;
        #pragma unroll
        for (int np = 0; np < 4; np++) brow[np] = (uint32_t)(wn * 64 + np * 16 + b_rowadd) * 128u;

        const float* cbS = (const float*)(sm + SM_BIAS);
        const float* brS = cbS + 128;
        const float* biS = cbS + 256;
        const float* lowS = (const float*)(sm + SM_LOW);
        float* red = (float*)(sm + SM_RED);

        for (int i = 0; i < nloc; i++) {
            int t = blockIdx.x + i * GRID_LAYER;
            int b, y, x0;
            decode_tile(t, b, y, x0);
            size_t base = ((size_t)(b * 256 + y)) * 256 + x0;

            float acc[2][8][4];
            #pragma unroll
            for (int mt = 0; mt < 2; mt++)
                #pragma unroll
                for (int nt = 0; nt < 8; nt++)
                    #pragma unroll
                    for (int q = 0; q < 4; q++) acc[mt][nt][q] = 0.0f;

            #pragma unroll
            for (int kc = 0; kc < 4; kc++) {
                int s = kc & 1;
                BAR_SYNC(1 + s, 512);
                uint32_t aHi = sbase + SM_A(s);
                uint32_t aLo = aHi + 16384u;
                uint32_t bHi = sbase + SM_BHI + (uint32_t)kc * 16384u;
                uint32_t bLo = bHi + 65536u;

                #pragma unroll
                for (int ks = 0; ks < 4; ks++) {
                    uint32_t acb = ((uint32_t)(ks * 32) + a_c16) ^ xm;
                    uint32_t bcb = ((uint32_t)(ks * 32) + b_c16) ^ xm;
                    uint32_t ah[2][4], al[2][4];
                    #pragma unroll
                    for (int mt = 0; mt < 2; mt++) {
                        ldsm4(ah[mt][0], ah[mt][1], ah[mt][2], ah[mt][3], aHi + arow[mt] + acb);
                        ldsm4(al[mt][0], al[mt][1], al[mt][2], al[mt][3], aLo + arow[mt] + acb);
                    }
                    #pragma unroll
                    for (int np = 0; np < 4; np++) {
                        uint32_t bh[4], bl[4];
                        ldsm4(bh[0], bh[1], bh[2], bh[3], bHi + brow[np] + bcb);
                        ldsm4(bl[0], bl[1], bl[2], bl[3], bLo + brow[np] + bcb);
                        #pragma unroll
                        for (int mt = 0; mt < 2; mt++) {
                            mma16816(acc[mt][np * 2],     ah[mt], bh[0], bh[1]);
                            mma16816(acc[mt][np * 2 + 1], ah[mt], bh[2], bh[3]);
                            mma16816(acc[mt][np * 2],     ah[mt], bl[0], bl[1]);
                            mma16816(acc[mt][np * 2 + 1], ah[mt], bl[2], bl[3]);
                            mma16816(acc[mt][np * 2],     al[mt], bh[0], bh[1]);
                            mma16816(acc[mt][np * 2 + 1], al[mt], bh[2], bh[3]);
                        }
                    }
                }
                BAR_ARRIVE(3 + s, 512);
            }

            // ---- epilogue ----
            bool row0 = (y == 0);
            if (!fuse) {
                #pragma unroll
                for (int mt = 0; mt < 2; mt++) {
                    #pragma unroll
                    for (int rh = 0; rh < 2; rh++) {
                        int m = wm * 32 + mt * 16 + (lane >> 2) + rh * 8;
                        int xx = x0 + m;
                        float sxv = row0 ? g_sx[xx] : 0.0f;
                        float* orow = hout + (base + m) * 128;
                        #pragma unroll
                        for (int nt = 0; nt < 8; nt++) {
                            int n = wn * 64 + nt * 8 + (lane & 3) * 2;
                            float v0 = acc[mt][nt][rh * 2]     + cbS[n];
                            float v1 = acc[mt][nt][rh * 2 + 1] + cbS[n + 1];
                            if (row0) {
                                v0 += biS[n] * sxv;
                                v1 += biS[n + 1] * sxv;
                                if (xx == 0) { v0 += brS[n]; v1 += brS[n + 1]; }
                            }
                            float2 o;
                            o.x = gelu_exact(v0);
                            o.y = gelu_exact(v1);
                            *(float2*)(orow + n) = o;
                        }
                    }
                }
            } else {
                // fused final layer: out[pix] = gelu( sum_n gelu(v_n)*low[n] + lob )
                float part[2][2];
                #pragma unroll
                for (int mt = 0; mt < 2; mt++) {
                    #pragma unroll
                    for (int rh = 0; rh < 2; rh++) {
                        int m = wm * 32 + mt * 16 + (lane >> 2) + rh * 8;
                        int xx = x0 + m;
                        float sxv = row0 ? g_sx[xx] : 0.0f;
                        float p = 0.0f;
                        #pragma unroll
                        for (int nt = 0; nt < 8; nt++) {
                            int n = wn * 64 + nt * 8 + (lane & 3) * 2;
                            float v0 = acc[mt][nt][rh * 2]     + cbS[n];
                            float v1 = acc[mt][nt][rh * 2 + 1] + cbS[n + 1];
                            if (row0) {
                                v0 += biS[n] * sxv;
                                v1 += biS[n + 1] * sxv;
                                if (xx == 0) { v0 += brS[n]; v1 += brS[n + 1]; }
                            }
                            p += gelu_exact(v0) * lowS[n] + gelu_exact(v1) * lowS[n + 1];
                        }
                        p += __shfl_xor_sync(0xffffffffu, p, 1);
                        p += __shfl_xor_sync(0xffffffffu, p, 2);
                        part[mt][rh] = p;
                    }
                }
                if ((lane & 3) == 0) {
                    #pragma unroll
                    for (int mt = 0; mt < 2; mt++)
                        #pragma unroll
                        for (int rh = 0; rh < 2; rh++) {
                            int m = wm * 32 + mt * 16 + (lane >> 2) + rh * 8;
                            red[wn * 128 + m] = part[mt][rh];
                        }
                }
                BAR_SYNC(5, 256);
                if (tid < 128) {
                    float lobv = lowS[128];
                    gout[base + tid] = gelu_exact(red[tid] + red[128 + tid] + lobv);
                }
                BAR_SYNC(5, 256);
            }
        }
    }
}

// ---------------------------------------------------------------------------
extern "C" void kernel_launch(void* const* d_in, const int* in_sizes, int n_in,
                              void* d_out, int out_size)
{
    const float* x   = (const float*)d_in[0];
    const float* liw = (const float*)d_in[1];
    const float* lib = (const float*)d_in[2];
    const float* wr  = (const float*)d_in[3];
    const float* wi  = (const float*)d_in[4];
    const float* br  = (const float*)d_in[5];
    const float* bi  = (const float*)d_in[6];
    const float* cw  = (const float*)d_in[7];
    const float* cb  = (const float*)d_in[8];
    const float* low = (const float*)d_in[9];
    const float* lob = (const float*)d_in[10];
    float* out = (float*)d_out;

    float *buf0, *buf1, *sx;
    unsigned short *whi, *wlo;
    cudaGetSymbolAddress((void**)&buf0, g_buf0);
    cudaGetSymbolAddress((void**)&buf1, g_buf1);
    cudaGetSymbolAddress((void**)&whi, g_whi);
    cudaGetSymbolAddress((void**)&wlo, g_wlo);
    cudaGetSymbolAddress((void**)&sx, g_sx);

    cudaFuncSetAttribute(layer_kernel, cudaFuncAttributeMaxDynamicSharedMemorySize, SM_DYN);

    prep_w_kernel<<<512, 256>>>(wr, wi, cw, whi, wlo);
    prep_sx_kernel<<<1, 256>>>(sx);
    in_kernel<<<NPIX * 32 / 256, 256>>>(x, liw, lib, buf0);

    float* bufs[2] = { buf0, buf1 };
    for (int l = 0; l < NL; l++) {
        int fuse = (l == NL - 1) ? 1 : 0;
        layer_kernel<<<GRID_LAYER, 512, SM_DYN>>>(
            bufs[l & 1], bufs[(l & 1) ^ 1],
            (const uint4*)(whi + (size_t)l * 4 * 8192),
            (const uint4*)(wlo + (size_t)l * 4 * 8192),
            cb + l * HID, br + l * HID, bi + l * HID,
            low, lob, out, fuse);
    }
}